// round 1
// baseline (speedup 1.0000x reference)
#include <cuda_runtime.h>
#include <math.h>

#define EPS 1e-6f
#define TB 16

// Per-triangle plane: (nx, ny, nz, d)  with plane eq  n.x + d = 0  through v0.
__device__ float4 g_nrm[4096];

__global__ void normals_kernel(const float* __restrict__ T, int N) {
    int i = blockIdx.x * blockDim.x + threadIdx.x;
    if (i >= N) return;
    const float* t = T + (size_t)i * 9;
    float v0x = t[0], v0y = t[1], v0z = t[2];
    float e1x = t[3] - v0x, e1y = t[4] - v0y, e1z = t[5] - v0z;
    float e2x = t[6] - v0x, e2y = t[7] - v0y, e2z = t[8] - v0z;
    float nx = e1y * e2z - e1z * e2y;
    float ny = e1z * e2x - e1x * e2z;
    float nz = e1x * e2y - e1y * e2x;
    float d = -(nx * v0x + ny * v0y + nz * v0z);
    g_nrm[i] = make_float4(nx, ny, nz, d);
}

__device__ __forceinline__ void interval3(const float p[3], const float d[3],
                                          float& tmin, float& tmax) {
    tmin = INFINITY;
    tmax = -INFINITY;
#pragma unroll
    for (int k = 0; k < 3; k++) {
        const int kn = (k == 2) ? 0 : k + 1;
        float di = d[k], dj = d[kn];
        float pi = p[k], pj = p[kn];
        bool valid = (di * dj <= 0.0f) && !((di == 0.0f) && (dj == 0.0f));
        float denom = di - dj;
        float t = pi + (pj - pi) * di / ((denom == 0.0f) ? 1.0f : denom);
        if (valid) {
            tmin = fminf(tmin, t);
            tmax = fmaxf(tmax, t);
        }
    }
}

__global__ void pair_kernel(const float* __restrict__ T,
                            float* __restrict__ out, int N) {
    const int ti = blockIdx.y, tj = blockIdx.x;
    if (tj < ti) return;  // upper-triangular tiles only

    __shared__ float trR[TB][9];
    __shared__ float trC[TB][9];
    __shared__ float4 nR[TB], nC[TB];
    __shared__ float res[TB][TB + 1];

    const int tx = threadIdx.x, ty = threadIdx.y;
    const int tid = ty * TB + tx;
    const int i0 = ti * TB, j0 = tj * TB;

    // Stage 16 row triangles + 16 col triangles (+planes) into shared.
    for (int k = tid; k < TB * 9; k += TB * TB) {
        int r = k / 9, c = k % 9;
        int gi = i0 + r, gj = j0 + r;
        trR[r][c] = (gi < N) ? T[(size_t)gi * 9 + c] : 0.0f;
        trC[r][c] = (gj < N) ? T[(size_t)gj * 9 + c] : 0.0f;
    }
    if (tid < TB) {
        nR[tid] = (i0 + tid < N) ? g_nrm[i0 + tid] : make_float4(0, 0, 0, 0);
    } else if (tid < 2 * TB) {
        int r = tid - TB;
        nC[r] = (j0 + r < N) ? g_nrm[j0 + r] : make_float4(0, 0, 0, 0);
    }
    __syncthreads();

    const int i = i0 + ty;  // row index  (reference "b")
    const int j = j0 + tx;  // col index  (reference "n")

    float r = 0.0f;
    if (j > i && i < N && j < N) {
        const float* A = trR[ty];  // triangle b
        const float* B = trC[tx];  // triangle n
        const float4 na = nR[ty];  // plane of b
        const float4 nb = nC[tx];  // plane of n

        // Signed distances with EPS snap (matches reference order of ops).
        float dv[3], du[3];
#pragma unroll
        for (int v = 0; v < 3; v++) {
            float dd = A[3 * v] * nb.x + A[3 * v + 1] * nb.y +
                       A[3 * v + 2] * nb.z + nb.w;
            dv[v] = (fabsf(dd) < EPS) ? 0.0f : dd;
            float ee = B[3 * v] * na.x + B[3 * v + 1] * na.y +
                       B[3 * v + 2] * na.z + na.w;
            du[v] = (fabsf(ee) < EPS) ? 0.0f : ee;
        }

        bool ssv = (dv[0] > 0 && dv[1] > 0 && dv[2] > 0) ||
                   (dv[0] < 0 && dv[1] < 0 && dv[2] < 0);
        bool ssu = (du[0] > 0 && du[1] > 0 && du[2] > 0) ||
                   (du[0] < 0 && du[1] < 0 && du[2] < 0);

        if (!(ssv || ssu)) {
            // Intersection-line direction; dominant axis (first max, like argmax).
            float Dx = na.y * nb.z - na.z * nb.y;
            float Dy = na.z * nb.x - na.x * nb.z;
            float Dz = na.x * nb.y - na.y * nb.x;
            int ax = 0;
            float m = fabsf(Dx);
            if (fabsf(Dy) > m) { ax = 1; m = fabsf(Dy); }
            if (fabsf(Dz) > m) { ax = 2; }

            float pv[3] = {A[ax], A[3 + ax], A[6 + ax]};
            float pu[3] = {B[ax], B[3 + ax], B[6 + ax]};

            float t0v, t1v, t0u, t1u;
            interval3(pv, dv, t0v, t1v);
            interval3(pu, du, t0u, t1u);
            if (fmaxf(t0v, t0u) <= fminf(t1v, t1u)) r = 1.0f;
        }
    }

    res[ty][tx] = r;
    __syncthreads();

    // Upper (and diagonal) tile: coalesced row writes.
    if (i < N && j < N) {
        float val;
        if (ti == tj) {
            val = (tx > ty) ? res[ty][tx] : ((tx == ty) ? 1.0f : res[tx][ty]);
        } else {
            val = res[ty][tx];
        }
        out[(size_t)i * N + j] = val;
    }
    // Mirror tile for strictly-off-diagonal blocks (also coalesced).
    if (ti != tj) {
        int jj = j0 + ty, ii = i0 + tx;
        if (jj < N && ii < N) out[(size_t)jj * N + ii] = res[tx][ty];
    }
}

extern "C" void kernel_launch(void* const* d_in, const int* in_sizes, int n_in,
                              void* d_out, int out_size) {
    const float* T = (const float*)d_in[0];
    float* out = (float*)d_out;
    int N = in_sizes[0] / 9;

    normals_kernel<<<(N + 255) / 256, 256>>>(T, N);

    dim3 blk(TB, TB);
    int nt = (N + TB - 1) / TB;
    dim3 grd(nt, nt);
    pair_kernel<<<grd, blk>>>(T, out, N);
}

// round 2
// speedup vs baseline: 1.1509x; 1.1509x over previous
#include <cuda_runtime.h>
#include <math.h>

#define EPS 1e-6f
#define TB 16

__device__ __forceinline__ void interval3(const float p[3], const float d[3],
                                          float& tmin, float& tmax) {
    tmin = INFINITY;
    tmax = -INFINITY;
#pragma unroll
    for (int k = 0; k < 3; k++) {
        const int kn = (k == 2) ? 0 : k + 1;
        float di = d[k], dj = d[kn];
        float pi = p[k], pj = p[kn];
        bool valid = (di * dj <= 0.0f) && !((di == 0.0f) && (dj == 0.0f));
        float denom = di - dj;
        float t = pi + (pj - pi) * __fdividef(di, (denom == 0.0f) ? 1.0f : denom);
        if (valid) {
            tmin = fminf(tmin, t);
            tmax = fmaxf(tmax, t);
        }
    }
}

// Compute plane (n, d) for a triangle stored as 9 floats in shared.
__device__ __forceinline__ float4 plane_of(const float* t) {
    float v0x = t[0], v0y = t[1], v0z = t[2];
    float e1x = t[3] - v0x, e1y = t[4] - v0y, e1z = t[5] - v0z;
    float e2x = t[6] - v0x, e2y = t[7] - v0y, e2z = t[8] - v0z;
    float nx = e1y * e2z - e1z * e2y;
    float ny = e1z * e2x - e1x * e2z;
    float nz = e1x * e2y - e1y * e2x;
    float d = -(nx * v0x + ny * v0y + nz * v0z);
    return make_float4(nx, ny, nz, d);
}

__global__ void pair_kernel(const float* __restrict__ T,
                            float* __restrict__ out, int N, int nt) {
    // Linear block index -> upper-triangular tile (ti <= tj):
    //   k = tj*(tj+1)/2 + ti,  ti in [0, tj]
    const int k = blockIdx.x;
    int tj = (int)((sqrtf(8.0f * (float)k + 1.0f) - 1.0f) * 0.5f);
    while ((tj + 1) * (tj + 2) / 2 <= k) tj++;
    while (tj * (tj + 1) / 2 > k) tj--;
    const int ti = k - tj * (tj + 1) / 2;

    __shared__ float trR[TB][9];
    __shared__ float trC[TB][9];
    __shared__ float4 nR[TB], nC[TB];
    __shared__ float res[TB][TB + 1];

    const int tx = threadIdx.x, ty = threadIdx.y;
    const int tid = ty * TB + tx;
    const int i0 = ti * TB, j0 = tj * TB;

    // Stage 16 row triangles + 16 col triangles into shared.
    for (int q = tid; q < TB * 9; q += TB * TB) {
        int r = q / 9, c = q % 9;
        int gi = i0 + r, gj = j0 + r;
        trR[r][c] = (gi < N) ? T[(size_t)gi * 9 + c] : 0.0f;
        trC[r][c] = (gj < N) ? T[(size_t)gj * 9 + c] : 0.0f;
    }
    __syncthreads();

    // 32 threads compute the 32 planes (fused normals pass).
    if (tid < TB) {
        nR[tid] = plane_of(trR[tid]);
    } else if (tid < 2 * TB) {
        nC[tid - TB] = plane_of(trC[tid - TB]);
    }
    __syncthreads();

    const int i = i0 + ty;  // row index  (reference "b")
    const int j = j0 + tx;  // col index  (reference "n")

    float r = 0.0f;
    if (j > i && i < N && j < N) {
        const float* A = trR[ty];  // triangle b
        const float* B = trC[tx];  // triangle n
        const float4 na = nR[ty];  // plane of b
        const float4 nb = nC[tx];  // plane of n

        // Signed distances with EPS snap (matches reference order of ops).
        float dv[3], du[3];
#pragma unroll
        for (int v = 0; v < 3; v++) {
            float dd = A[3 * v] * nb.x + A[3 * v + 1] * nb.y +
                       A[3 * v + 2] * nb.z + nb.w;
            dv[v] = (fabsf(dd) < EPS) ? 0.0f : dd;
            float ee = B[3 * v] * na.x + B[3 * v + 1] * na.y +
                       B[3 * v + 2] * na.z + na.w;
            du[v] = (fabsf(ee) < EPS) ? 0.0f : ee;
        }

        bool ssv = (dv[0] > 0 && dv[1] > 0 && dv[2] > 0) ||
                   (dv[0] < 0 && dv[1] < 0 && dv[2] < 0);
        bool ssu = (du[0] > 0 && du[1] > 0 && du[2] > 0) ||
                   (du[0] < 0 && du[1] < 0 && du[2] < 0);

        if (!(ssv || ssu)) {
            // Intersection-line direction; dominant axis (first-max, like argmax).
            float Dx = na.y * nb.z - na.z * nb.y;
            float Dy = na.z * nb.x - na.x * nb.z;
            float Dz = na.x * nb.y - na.y * nb.x;
            int ax = 0;
            float m = fabsf(Dx);
            if (fabsf(Dy) > m) { ax = 1; m = fabsf(Dy); }
            if (fabsf(Dz) > m) { ax = 2; }

            float pv[3] = {A[ax], A[3 + ax], A[6 + ax]};
            float pu[3] = {B[ax], B[3 + ax], B[6 + ax]};

            float t0v, t1v, t0u, t1u;
            interval3(pv, dv, t0v, t1v);
            interval3(pu, du, t0u, t1u);
            if (fmaxf(t0v, t0u) <= fminf(t1v, t1u)) r = 1.0f;
        }
    }

    res[ty][tx] = r;
    __syncthreads();

    // Upper (and diagonal) tile: coalesced row writes.
    if (i < N && j < N) {
        float val;
        if (ti == tj) {
            val = (tx > ty) ? res[ty][tx] : ((tx == ty) ? 1.0f : res[tx][ty]);
        } else {
            val = res[ty][tx];
        }
        out[(size_t)i * N + j] = val;
    }
    // Mirror tile for strictly-off-diagonal blocks (also coalesced).
    if (ti != tj) {
        int jj = j0 + ty, ii = i0 + tx;
        if (jj < N && ii < N) out[(size_t)jj * N + ii] = res[tx][ty];
    }
}

extern "C" void kernel_launch(void* const* d_in, const int* in_sizes, int n_in,
                              void* d_out, int out_size) {
    const float* T = (const float*)d_in[0];
    float* out = (float*)d_out;
    int N = in_sizes[0] / 9;

    int nt = (N + TB - 1) / TB;
    int nblk = nt * (nt + 1) / 2;
    dim3 blk(TB, TB);
    pair_kernel<<<nblk, blk>>>(T, out, N, nt);
}